// round 2
// baseline (speedup 1.0000x reference)
#include <cuda_runtime.h>
#include <cstdint>

// ---------------- problem constants ----------------
#define S  2048
#define E  1024
#define H  1024
#define V  32000

// ---------------- device scratch (no allocs allowed) ----------------
__device__ __align__(16) float g_gates[4 * H];
__device__ __align__(16) float g_h[H];
__device__ __align__(16) float g_c[H];
__device__ __align__(16) float g_u[H];        // W_att[:, :H] @ h + b_att
__device__ __align__(16) float g_scores[S];
__device__ __align__(16) float g_w[S];
__device__ __align__(16) float g_context[E];
__device__ __align__(16) float g_xt[H];
__device__ __align__(16) float g_lse[2];

__device__ __forceinline__ float sigf(float x) { return 1.0f / (1.0f + expf(-x)); }

__device__ __forceinline__ float warp_sum(float s) {
#pragma unroll
    for (int o = 16; o; o >>= 1) s += __shfl_xor_sync(0xFFFFFFFFu, s, o);
    return s;
}

// ---------------- K1: LSTM gates matvec ----------------
// gates[r] = W_ih[r,:H]@last_ctx + W_ih[r,H:]@emb_row + W_hh[r]@h0 + b_ih + b_hh
// grid: 512 blocks x 256 threads (8 warps -> 8 rows/block), 4096 rows total
__global__ void k_gates(const float* __restrict__ W_ih, const float* __restrict__ b_ih,
                        const float* __restrict__ W_hh, const float* __restrict__ b_hh,
                        const float* __restrict__ last_ctx, const float* __restrict__ emb,
                        const int* __restrict__ word, const float* __restrict__ h0) {
    int r    = blockIdx.x * 8 + (threadIdx.x >> 5);
    int lane = threadIdx.x & 31;
    const float4* xe4 = (const float4*)(emb + (size_t)word[0] * E);
    const float4* lc4 = (const float4*)last_ctx;
    const float4* h04 = (const float4*)h0;
    const float4* wi4 = (const float4*)(W_ih + (size_t)r * (E + H));
    const float4* wh4 = (const float4*)(W_hh + (size_t)r * H);

    float s = 0.f;
#pragma unroll
    for (int q = 0; q < 8; q++) {
        int k = lane + 32 * q;
        float4 a = wi4[k];       float4 b = lc4[k];
        s += a.x * b.x + a.y * b.y + a.z * b.z + a.w * b.w;
        float4 a2 = wi4[256 + k]; float4 b2 = xe4[k];
        s += a2.x * b2.x + a2.y * b2.y + a2.z * b2.z + a2.w * b2.w;
        float4 a3 = wh4[k];      float4 b3 = h04[k];
        s += a3.x * b3.x + a3.y * b3.y + a3.z * b3.z + a3.w * b3.w;
    }
    s = warp_sum(s);
    if (lane == 0) g_gates[r] = s + b_ih[r] + b_hh[r];
}

// ---------------- K2: LSTM cell elementwise + scratch zeroing ----------------
// 1 block x 1024 threads
__global__ void k_cell(const float* __restrict__ c0, float* __restrict__ out) {
    int t = threadIdx.x;
    float ig = sigf(g_gates[t]);
    float fg = sigf(g_gates[H + t]);
    float gg = tanhf(g_gates[2 * H + t]);
    float og = sigf(g_gates[3 * H + t]);
    float c  = fg * c0[t] + ig * gg;
    float h  = og * tanhf(c);
    g_h[t] = h;
    g_c[t] = c;
    out[V + t]     = h;   // h slot
    out[V + H + t] = c;   // c slot
    g_context[t] = 0.f;
    g_scores[t] = 0.f;
    g_scores[H + t] = 0.f;
}

// ---------------- K2b: u = W_att[:, :H] @ h + b_att ----------------
// grid: 128 blocks x 256 threads (warp per row, 1024 rows)
__global__ void k_u(const float* __restrict__ W_att, const float* __restrict__ b_att) {
    int r    = blockIdx.x * 8 + (threadIdx.x >> 5);
    int lane = threadIdx.x & 31;
    const float4* wa4 = (const float4*)(W_att + (size_t)r * (H + E));
    const float4* h4  = (const float4*)g_h;
    float s = 0.f;
#pragma unroll
    for (int q = 0; q < 8; q++) {
        int k = lane + 32 * q;
        float4 a = wa4[k]; float4 b = h4[k];
        s += a.x * b.x + a.y * b.y + a.z * b.z + a.w * b.w;
    }
    s = warp_sum(s);
    if (lane == 0) g_u[r] = s + b_att[r];
}

// ---------------- K3: attention GEMM + fused tanh/v reduction ----------------
// C[s,h] = sum_k enc[s,k] * W_att[h, H+k];  scores[s] += sum_h v[h]*tanh(C+u[h])
// Tile 128(s) x 128(h), K-step 16, 256 threads, 8x8 micro. grid (16, 8).
#define BK 16
#define PAD 4
__global__ void __launch_bounds__(256, 1)
k_att(const float* __restrict__ enc, const float* __restrict__ W_att,
      const float* __restrict__ v) {
    __shared__ float As[BK][128 + PAD];
    __shared__ float Bs[BK][128 + PAD];
    __shared__ float sacc[128];

    int tid = threadIdx.x;
    int tx = tid & 15;           // h micro index
    int ty = tid >> 4;           // s micro index
    int s0 = blockIdx.x * 128;
    int h0 = blockIdx.y * 128;

    float acc[8][8];
#pragma unroll
    for (int r = 0; r < 8; r++)
#pragma unroll
        for (int c = 0; c < 8; c++) acc[r][c] = 0.f;

    for (int k0 = 0; k0 < E; k0 += BK) {
#pragma unroll
        for (int l = 0; l < 2; l++) {
            int idx = tid + 256 * l;          // 0..511
            int row = idx >> 2;               // 0..127
            int q   = idx & 3;                // 0..3 (quad of 4 k's)
            float4 av = *(const float4*)(enc + (size_t)(s0 + row) * E + k0 + q * 4);
            As[q * 4 + 0][row] = av.x; As[q * 4 + 1][row] = av.y;
            As[q * 4 + 2][row] = av.z; As[q * 4 + 3][row] = av.w;
            float4 bv = *(const float4*)(W_att + (size_t)(h0 + row) * (H + E) + H + k0 + q * 4);
            Bs[q * 4 + 0][row] = bv.x; Bs[q * 4 + 1][row] = bv.y;
            Bs[q * 4 + 2][row] = bv.z; Bs[q * 4 + 3][row] = bv.w;
        }
        __syncthreads();
#pragma unroll
        for (int j = 0; j < BK; j++) {
            float a[8], b[8];
            *(float4*)(a)     = *(const float4*)&As[j][ty * 8];
            *(float4*)(a + 4) = *(const float4*)&As[j][ty * 8 + 4];
            *(float4*)(b)     = *(const float4*)&Bs[j][tx * 8];
            *(float4*)(b + 4) = *(const float4*)&Bs[j][tx * 8 + 4];
#pragma unroll
            for (int r = 0; r < 8; r++)
#pragma unroll
                for (int c = 0; c < 8; c++) acc[r][c] += a[r] * b[c];
        }
        __syncthreads();
    }

    // epilogue: partial[s] = sum over this thread's 8 h of v[h]*tanh(acc + u[h])
    float part[8];
#pragma unroll
    for (int r = 0; r < 8; r++) part[r] = 0.f;
#pragma unroll
    for (int c = 0; c < 8; c++) {
        int h = h0 + tx * 8 + c;
        float uv = g_u[h];
        float vv = v[h];
#pragma unroll
        for (int r = 0; r < 8; r++) part[r] += vv * tanhf(acc[r][c] + uv);
    }
    if (tid < 128) sacc[tid] = 0.f;
    __syncthreads();
#pragma unroll
    for (int r = 0; r < 8; r++) atomicAdd(&sacc[ty * 8 + r], part[r]);
    __syncthreads();
    if (tid < 128) atomicAdd(&g_scores[s0 + tid], sacc[tid]);
}

// ---------------- K4: softmax over scores[2048] -> w ----------------
// 1 block x 256 threads
__global__ void k_softmax(float* __restrict__ out) {
    __shared__ float red[256];
    int t = threadIdx.x;
    float m = -1e30f;
    for (int s = t; s < S; s += 256) m = fmaxf(m, g_scores[s]);
    red[t] = m; __syncthreads();
    for (int o = 128; o; o >>= 1) { if (t < o) red[t] = fmaxf(red[t], red[t + o]); __syncthreads(); }
    m = red[0]; __syncthreads();
    float sum = 0.f;
    for (int s = t; s < S; s += 256) sum += expf(g_scores[s] - m);
    red[t] = sum; __syncthreads();
    for (int o = 128; o; o >>= 1) { if (t < o) red[t] += red[t + o]; __syncthreads(); }
    float tot = red[0];
    float inv = 1.0f / tot;
    for (int s = t; s < S; s += 256) {
        float w = expf(g_scores[s] - m) * inv;
        g_w[s] = w;
        out[V + 3 * H + s] = w;  // w slot
    }
}

// ---------------- K5: context = w @ enc ----------------
// grid (4 e-chunks, 8 s-chunks) x 256 threads, atomicAdd into g_context
__global__ void k_context(const float* __restrict__ enc) {
    int e = blockIdx.x * 256 + threadIdx.x;
    int s0 = blockIdx.y * 256;
    float acc = 0.f;
    for (int s = s0; s < s0 + 256; s++)
        acc += g_w[s] * enc[(size_t)s * E + e];
    atomicAdd(&g_context[e], acc);
}

// ---------------- K6: x_t = tanh(W_ah @ [context, h] + b_ah) ----------------
// grid: 128 blocks x 256 threads (warp per row)
__global__ void k_xt(const float* __restrict__ W_ah, const float* __restrict__ b_ah,
                     float* __restrict__ out) {
    int r    = blockIdx.x * 8 + (threadIdx.x >> 5);
    int lane = threadIdx.x & 31;
    const float4* wa4 = (const float4*)(W_ah + (size_t)r * (E + H));
    const float4* c4  = (const float4*)g_context;
    const float4* h4  = (const float4*)g_h;
    float s = 0.f;
#pragma unroll
    for (int q = 0; q < 8; q++) {
        int k = lane + 32 * q;
        float4 a = wa4[k];        float4 b = c4[k];
        s += a.x * b.x + a.y * b.y + a.z * b.z + a.w * b.w;
        float4 a2 = wa4[256 + k]; float4 b2 = h4[k];
        s += a2.x * b2.x + a2.y * b2.y + a2.z * b2.z + a2.w * b2.w;
    }
    s = warp_sum(s);
    if (lane == 0) {
        float xt = tanhf(s + b_ah[r]);
        g_xt[r] = xt;
        out[V + 2 * H + r] = xt;  // x_t slot
    }
}

// ---------------- K7: logits = W_out @ x_t + b_out (write into out[0:V]) ----------------
// grid: 4000 blocks x 256 threads (warp per row, 32000 rows)
__global__ void k_logits(const float* __restrict__ W_out, const float* __restrict__ b_out,
                         float* __restrict__ out) {
    int r    = blockIdx.x * 8 + (threadIdx.x >> 5);
    int lane = threadIdx.x & 31;
    const float4* w4 = (const float4*)(W_out + (size_t)r * H);
    const float4* x4 = (const float4*)g_xt;
    float s = 0.f;
#pragma unroll
    for (int q = 0; q < 8; q++) {
        int k = lane + 32 * q;
        float4 a = w4[k]; float4 b = x4[k];
        s += a.x * b.x + a.y * b.y + a.z * b.z + a.w * b.w;
    }
    s = warp_sum(s);
    if (lane == 0) out[r] = s + b_out[r];
}

// ---------------- K8: log-sum-exp over logits ----------------
// 1 block x 256 threads
__global__ void k_lse(const float* __restrict__ out) {
    __shared__ float red[256];
    int t = threadIdx.x;
    float m = -1e30f;
    for (int i = t; i < V; i += 256) m = fmaxf(m, out[i]);
    red[t] = m; __syncthreads();
    for (int o = 128; o; o >>= 1) { if (t < o) red[t] = fmaxf(red[t], red[t + o]); __syncthreads(); }
    m = red[0]; __syncthreads();
    float sum = 0.f;
    for (int i = t; i < V; i += 256) sum += expf(out[i] - m);
    red[t] = sum; __syncthreads();
    for (int o = 128; o; o >>= 1) { if (t < o) red[t] += red[t + o]; __syncthreads(); }
    if (t == 0) { g_lse[0] = m; g_lse[1] = logf(red[0]); }
}

// ---------------- K9: out[i] = logit - max - log(sumexp) ----------------
__global__ void k_logsoftmax(float* __restrict__ out) {
    int i = blockIdx.x * 256 + threadIdx.x;
    if (i < V) out[i] = out[i] - g_lse[0] - g_lse[1];
}

// ---------------- launch ----------------
extern "C" void kernel_launch(void* const* d_in, const int* in_sizes, int n_in,
                              void* d_out, int out_size) {
    const float* enc      = (const float*)d_in[0];
    const int*   word     = (const int*)  d_in[1];
    const float* last_ctx = (const float*)d_in[2];
    const float* h0       = (const float*)d_in[3];
    const float* c0       = (const float*)d_in[4];
    const float* emb      = (const float*)d_in[5];
    const float* W_ih     = (const float*)d_in[6];
    const float* b_ih     = (const float*)d_in[7];
    const float* W_hh     = (const float*)d_in[8];
    const float* b_hh     = (const float*)d_in[9];
    const float* W_att    = (const float*)d_in[10];
    const float* b_att    = (const float*)d_in[11];
    const float* v        = (const float*)d_in[12];
    const float* W_ah     = (const float*)d_in[13];
    const float* b_ah     = (const float*)d_in[14];
    const float* W_out    = (const float*)d_in[15];
    const float* b_out    = (const float*)d_in[16];
    float* out = (float*)d_out;

    k_gates<<<512, 256>>>(W_ih, b_ih, W_hh, b_hh, last_ctx, emb, word, h0);
    k_cell<<<1, 1024>>>(c0, out);
    k_u<<<128, 256>>>(W_att, b_att);
    dim3 g3(S / 128, H / 128);
    k_att<<<g3, 256>>>(enc, W_att, v);
    k_softmax<<<1, 256>>>(out);
    dim3 g5(E / 256, S / 256);
    k_context<<<g5, 256>>>(enc);
    k_xt<<<128, 256>>>(W_ah, b_ah, out);
    k_logits<<<V / 8, 256>>>(W_out, b_out, out);
    k_lse<<<1, 256>>>(out);
    k_logsoftmax<<<(V + 255) / 256, 256>>>(out);
}

// round 4
// speedup vs baseline: 1.8596x; 1.8596x over previous
#include <cuda_runtime.h>
#include <cstdint>

// ---------------- problem constants ----------------
#define S  2048
#define E  1024
#define H  1024
#define V  32000

// ---------------- device scratch (no allocs allowed) ----------------
__device__ __align__(16) float g_gates[4 * H];
__device__ __align__(16) float g_h[H];
__device__ __align__(16) float g_c[H];
__device__ __align__(16) float g_u[H];        // W_att[:, :H] @ h + b_att
__device__ __align__(16) float g_scores[S];
__device__ __align__(16) float g_w[S];
__device__ __align__(16) float g_context[E];
__device__ __align__(16) float g_xt[H];
__device__ __align__(16) float g_lse[2];

__device__ __forceinline__ float sigf(float x) { return 1.0f / (1.0f + expf(-x)); }

__device__ __forceinline__ float warp_sum(float s) {
#pragma unroll
    for (int o = 16; o; o >>= 1) s += __shfl_xor_sync(0xFFFFFFFFu, s, o);
    return s;
}

__device__ __forceinline__ uint32_t f2tf(float x) {
    uint32_t r;
    asm("cvt.rna.tf32.f32 %0, %1;" : "=r"(r) : "f"(x));
    return r;
}

__device__ __forceinline__ void mma_tf32(float* c, const uint32_t* a, uint32_t b0, uint32_t b1) {
    asm volatile(
        "mma.sync.aligned.m16n8k8.row.col.f32.tf32.tf32.f32 "
        "{%0,%1,%2,%3}, {%4,%5,%6,%7}, {%8,%9}, {%0,%1,%2,%3};\n"
        : "+f"(c[0]), "+f"(c[1]), "+f"(c[2]), "+f"(c[3])
        : "r"(a[0]), "r"(a[1]), "r"(a[2]), "r"(a[3]), "r"(b0), "r"(b1));
}

// ---------------- K1: LSTM gates matvec ----------------
__global__ void k_gates(const float* __restrict__ W_ih, const float* __restrict__ b_ih,
                        const float* __restrict__ W_hh, const float* __restrict__ b_hh,
                        const float* __restrict__ last_ctx, const float* __restrict__ emb,
                        const int* __restrict__ word, const float* __restrict__ h0) {
    int r    = blockIdx.x * 8 + (threadIdx.x >> 5);
    int lane = threadIdx.x & 31;
    const float4* xe4 = (const float4*)(emb + (size_t)word[0] * E);
    const float4* lc4 = (const float4*)last_ctx;
    const float4* h04 = (const float4*)h0;
    const float4* wi4 = (const float4*)(W_ih + (size_t)r * (E + H));
    const float4* wh4 = (const float4*)(W_hh + (size_t)r * H);

    float s = 0.f;
#pragma unroll
    for (int q = 0; q < 8; q++) {
        int k = lane + 32 * q;
        float4 a = wi4[k];       float4 b = lc4[k];
        s += a.x * b.x + a.y * b.y + a.z * b.z + a.w * b.w;
        float4 a2 = wi4[256 + k]; float4 b2 = xe4[k];
        s += a2.x * b2.x + a2.y * b2.y + a2.z * b2.z + a2.w * b2.w;
        float4 a3 = wh4[k];      float4 b3 = h04[k];
        s += a3.x * b3.x + a3.y * b3.y + a3.z * b3.z + a3.w * b3.w;
    }
    s = warp_sum(s);
    if (lane == 0) g_gates[r] = s + b_ih[r] + b_hh[r];
}

// ---------------- K2: LSTM cell elementwise + scratch zeroing ----------------
__global__ void k_cell(const float* __restrict__ c0, float* __restrict__ out) {
    int t = threadIdx.x;
    float ig = sigf(g_gates[t]);
    float fg = sigf(g_gates[H + t]);
    float gg = tanhf(g_gates[2 * H + t]);
    float og = sigf(g_gates[3 * H + t]);
    float c  = fg * c0[t] + ig * gg;
    float h  = og * tanhf(c);
    g_h[t] = h;
    g_c[t] = c;
    out[V + t]     = h;
    out[V + H + t] = c;
    g_context[t] = 0.f;
    g_scores[t] = 0.f;
    g_scores[H + t] = 0.f;
}

// ---------------- K2b: u = W_att[:, :H] @ h + b_att ----------------
__global__ void k_u(const float* __restrict__ W_att, const float* __restrict__ b_att) {
    int r    = blockIdx.x * 8 + (threadIdx.x >> 5);
    int lane = threadIdx.x & 31;
    const float4* wa4 = (const float4*)(W_att + (size_t)r * (H + E));
    const float4* h4  = (const float4*)g_h;
    float s = 0.f;
#pragma unroll
    for (int q = 0; q < 8; q++) {
        int k = lane + 32 * q;
        float4 a = wa4[k]; float4 b = h4[k];
        s += a.x * b.x + a.y * b.y + a.z * b.z + a.w * b.w;
    }
    s = warp_sum(s);
    if (lane == 0) g_u[r] = s + b_att[r];
}

// ---------------- K3: attention GEMM (tf32 tensor cores) + fused tanh/v reduction ----------------
// C[s,h] = sum_k enc[s,k] * W_att[h, H+k];  scores[s] += sum_h v[h]*tanh(C+u[h])
// Tile 128(s) x 128(h), K-chunk 32, 256 threads (8 warps, 2x4 warp grid, 64x32 per warp).
#define BM 128
#define BN 128
#define BKC 32
#define PADK 36

__global__ void __launch_bounds__(256, 1)
k_att_tc(const float* __restrict__ enc, const float* __restrict__ W_att,
         const float* __restrict__ v) {
    __shared__ uint32_t As[BM][PADK];   // tf32 bits, [s_local][k]
    __shared__ uint32_t Bs[BN][PADK];   // tf32 bits, [h_local][k]
    __shared__ float sacc[BM];

    int tid  = threadIdx.x;
    int wid  = tid >> 5;
    int lane = tid & 31;
    int warp_m = wid >> 2;      // 0..1
    int warp_n = wid & 3;       // 0..3
    int gid  = lane >> 2;       // 0..7
    int tid4 = lane & 3;        // 0..3
    int s0 = blockIdx.x * BM;
    int h0 = blockIdx.y * BN;

    float acc[4][4][4];
#pragma unroll
    for (int mt = 0; mt < 4; mt++)
#pragma unroll
        for (int nt = 0; nt < 4; nt++)
#pragma unroll
            for (int r = 0; r < 4; r++) acc[mt][nt][r] = 0.f;

    // staging registers for global->smem double buffering
    float4 stA[4], stB[4];
    int rows[4], c4s[4];
#pragma unroll
    for (int i = 0; i < 4; i++) {
        int f = tid + 256 * i;      // 0..1023
        rows[i] = f >> 3;
        c4s[i]  = f & 7;
    }

    // load chunk 0
#pragma unroll
    for (int i = 0; i < 4; i++) {
        stA[i] = *(const float4*)(enc   + (size_t)(s0 + rows[i]) * E + c4s[i] * 4);
        stB[i] = *(const float4*)(W_att + (size_t)(h0 + rows[i]) * (H + E) + H + c4s[i] * 4);
    }

    for (int kc = 0; kc < E / BKC; kc++) {
        __syncthreads();   // previous compute done reading smem
#pragma unroll
        for (int i = 0; i < 4; i++) {
            uint4 ua = make_uint4(f2tf(stA[i].x), f2tf(stA[i].y), f2tf(stA[i].z), f2tf(stA[i].w));
            *(uint4*)&As[rows[i]][c4s[i] * 4] = ua;
            uint4 ub = make_uint4(f2tf(stB[i].x), f2tf(stB[i].y), f2tf(stB[i].z), f2tf(stB[i].w));
            *(uint4*)&Bs[rows[i]][c4s[i] * 4] = ub;
        }
        __syncthreads();

        if (kc + 1 < E / BKC) {
            int k0 = (kc + 1) * BKC;
#pragma unroll
            for (int i = 0; i < 4; i++) {
                stA[i] = *(const float4*)(enc   + (size_t)(s0 + rows[i]) * E + k0 + c4s[i] * 4);
                stB[i] = *(const float4*)(W_att + (size_t)(h0 + rows[i]) * (H + E) + H + k0 + c4s[i] * 4);
            }
        }

#pragma unroll
        for (int ks = 0; ks < BKC / 8; ks++) {
            int kb = ks * 8;
            uint32_t af[4][4];
#pragma unroll
            for (int mt = 0; mt < 4; mt++) {
                int row = warp_m * 64 + mt * 16 + gid;
                af[mt][0] = As[row][kb + tid4];
                af[mt][1] = As[row + 8][kb + tid4];
                af[mt][2] = As[row][kb + tid4 + 4];
                af[mt][3] = As[row + 8][kb + tid4 + 4];
            }
#pragma unroll
            for (int nt = 0; nt < 4; nt++) {
                int col = warp_n * 32 + nt * 8 + gid;
                uint32_t b0 = Bs[col][kb + tid4];
                uint32_t b1 = Bs[col][kb + tid4 + 4];
#pragma unroll
                for (int mt = 0; mt < 4; mt++)
                    mma_tf32(acc[mt][nt], af[mt], b0, b1);
            }
        }
    }

    // ---- epilogue: scores[s] += sum_h v[h]*tanh(C[s,h]+u[h]) ----
    __syncthreads();
    if (tid < BM) sacc[tid] = 0.f;
    __syncthreads();

    float uu[4][2], vv[4][2];
#pragma unroll
    for (int nt = 0; nt < 4; nt++) {
        int h = h0 + warp_n * 32 + nt * 8 + 2 * tid4;
        uu[nt][0] = g_u[h];     uu[nt][1] = g_u[h + 1];
        vv[nt][0] = v[h];       vv[nt][1] = v[h + 1];
    }
#pragma unroll
    for (int mt = 0; mt < 4; mt++) {
        float r0 = 0.f, r1 = 0.f;
#pragma unroll
        for (int nt = 0; nt < 4; nt++) {
            r0 += vv[nt][0] * tanhf(acc[mt][nt][0] + uu[nt][0])
                + vv[nt][1] * tanhf(acc[mt][nt][1] + uu[nt][1]);
            r1 += vv[nt][0] * tanhf(acc[mt][nt][2] + uu[nt][0])
                + vv[nt][1] * tanhf(acc[mt][nt][3] + uu[nt][1]);
        }
        r0 += __shfl_xor_sync(0xFFFFFFFFu, r0, 1);
        r0 += __shfl_xor_sync(0xFFFFFFFFu, r0, 2);
        r1 += __shfl_xor_sync(0xFFFFFFFFu, r1, 1);
        r1 += __shfl_xor_sync(0xFFFFFFFFu, r1, 2);
        if (tid4 == 0) {
            atomicAdd(&sacc[warp_m * 64 + mt * 16 + gid], r0);
            atomicAdd(&sacc[warp_m * 64 + mt * 16 + gid + 8], r1);
        }
    }
    __syncthreads();
    if (tid < BM) atomicAdd(&g_scores[s0 + tid], sacc[tid]);
}

// ---------------- K4: softmax over scores[2048] -> w ----------------
__global__ void k_softmax(float* __restrict__ out) {
    __shared__ float red[256];
    int t = threadIdx.x;
    float m = -1e30f;
    for (int s = t; s < S; s += 256) m = fmaxf(m, g_scores[s]);
    red[t] = m; __syncthreads();
    for (int o = 128; o; o >>= 1) { if (t < o) red[t] = fmaxf(red[t], red[t + o]); __syncthreads(); }
    m = red[0]; __syncthreads();
    float sum = 0.f;
    for (int s = t; s < S; s += 256) sum += expf(g_scores[s] - m);
    red[t] = sum; __syncthreads();
    for (int o = 128; o; o >>= 1) { if (t < o) red[t] += red[t + o]; __syncthreads(); }
    float tot = red[0];
    float inv = 1.0f / tot;
    for (int s = t; s < S; s += 256) {
        float w = expf(g_scores[s] - m) * inv;
        g_w[s] = w;
        out[V + 3 * H + s] = w;
    }
}

// ---------------- K5: context = w @ enc ----------------
__global__ void k_context(const float* __restrict__ enc) {
    int e = blockIdx.x * 256 + threadIdx.x;
    int s0 = blockIdx.y * 256;
    float acc = 0.f;
    for (int s = s0; s < s0 + 256; s++)
        acc += g_w[s] * enc[(size_t)s * E + e];
    atomicAdd(&g_context[e], acc);
}

// ---------------- K6: x_t = tanh(W_ah @ [context, h] + b_ah) ----------------
__global__ void k_xt(const float* __restrict__ W_ah, const float* __restrict__ b_ah,
                     float* __restrict__ out) {
    int r    = blockIdx.x * 8 + (threadIdx.x >> 5);
    int lane = threadIdx.x & 31;
    const float4* wa4 = (const float4*)(W_ah + (size_t)r * (E + H));
    const float4* c4  = (const float4*)g_context;
    const float4* h4  = (const float4*)g_h;
    float s = 0.f;
#pragma unroll
    for (int q = 0; q < 8; q++) {
        int k = lane + 32 * q;
        float4 a = wa4[k];        float4 b = c4[k];
        s += a.x * b.x + a.y * b.y + a.z * b.z + a.w * b.w;
        float4 a2 = wa4[256 + k]; float4 b2 = h4[k];
        s += a2.x * b2.x + a2.y * b2.y + a2.z * b2.z + a2.w * b2.w;
    }
    s = warp_sum(s);
    if (lane == 0) {
        float xt = tanhf(s + b_ah[r]);
        g_xt[r] = xt;
        out[V + 2 * H + r] = xt;
    }
}

// ---------------- K7: logits = W_out @ x_t + b_out ----------------
__global__ void k_logits(const float* __restrict__ W_out, const float* __restrict__ b_out,
                         float* __restrict__ out) {
    int r    = blockIdx.x * 8 + (threadIdx.x >> 5);
    int lane = threadIdx.x & 31;
    const float4* w4 = (const float4*)(W_out + (size_t)r * H);
    const float4* x4 = (const float4*)g_xt;
    float s = 0.f;
#pragma unroll
    for (int q = 0; q < 8; q++) {
        int k = lane + 32 * q;
        float4 a = w4[k]; float4 b = x4[k];
        s += a.x * b.x + a.y * b.y + a.z * b.z + a.w * b.w;
    }
    s = warp_sum(s);
    if (lane == 0) out[r] = s + b_out[r];
}

// ---------------- K8: log-sum-exp over logits ----------------
__global__ void k_lse(const float* __restrict__ out) {
    __shared__ float red[256];
    int t = threadIdx.x;
    float m = -1e30f;
    for (int i = t; i < V; i += 256) m = fmaxf(m, out[i]);
    red[t] = m; __syncthreads();
    for (int o = 128; o; o >>= 1) { if (t < o) red[t] = fmaxf(red[t], red[t + o]); __syncthreads(); }
    m = red[0]; __syncthreads();
    float sum = 0.f;
    for (int i = t; i < V; i += 256) sum += expf(out[i] - m);
    red[t] = sum; __syncthreads();
    for (int o = 128; o; o >>= 1) { if (t < o) red[t] += red[t + o]; __syncthreads(); }
    if (t == 0) { g_lse[0] = m; g_lse[1] = logf(red[0]); }
}

// ---------------- K9: out[i] = logit - max - log(sumexp) ----------------
__global__ void k_logsoftmax(float* __restrict__ out) {
    int i = blockIdx.x * 256 + threadIdx.x;
    if (i < V) out[i] = out[i] - g_lse[0] - g_lse[1];
}

// ---------------- launch ----------------
extern "C" void kernel_launch(void* const* d_in, const int* in_sizes, int n_in,
                              void* d_out, int out_size) {
    const float* enc      = (const float*)d_in[0];
    const int*   word     = (const int*)  d_in[1];
    const float* last_ctx = (const float*)d_in[2];
    const float* h0       = (const float*)d_in[3];
    const float* c0       = (const float*)d_in[4];
    const float* emb      = (const float*)d_in[5];
    const float* W_ih     = (const float*)d_in[6];
    const float* b_ih     = (const float*)d_in[7];
    const float* W_hh     = (const float*)d_in[8];
    const float* b_hh     = (const float*)d_in[9];
    const float* W_att    = (const float*)d_in[10];
    const float* b_att    = (const float*)d_in[11];
    const float* v        = (const float*)d_in[12];
    const float* W_ah     = (const float*)d_in[13];
    const float* b_ah     = (const float*)d_in[14];
    const float* W_out    = (const float*)d_in[15];
    const float* b_out    = (const float*)d_in[16];
    float* out = (float*)d_out;

    k_gates<<<512, 256>>>(W_ih, b_ih, W_hh, b_hh, last_ctx, emb, word, h0);
    k_cell<<<1, 1024>>>(c0, out);
    k_u<<<128, 256>>>(W_att, b_att);
    dim3 g3(S / BM, H / BN);
    k_att_tc<<<g3, 256>>>(enc, W_att, v);
    k_softmax<<<1, 256>>>(out);
    dim3 g5(E / 256, S / 256);
    k_context<<<g5, 256>>>(enc);
    k_xt<<<128, 256>>>(W_ah, b_ah, out);
    k_logits<<<V / 8, 256>>>(W_out, b_out, out);
    k_lse<<<1, 256>>>(out);
    k_logsoftmax<<<(V + 255) / 256, 256>>>(out);
}

// round 5
// speedup vs baseline: 1.8992x; 1.0213x over previous
#include <cuda_runtime.h>
#include <cstdint>

// ---------------- problem constants ----------------
#define S  2048
#define E  1024
#define H  1024
#define V  32000

// ---------------- device scratch (no allocs allowed) ----------------
__device__ __align__(16) float g_gates[4 * H];
__device__ __align__(16) float g_h[H];
__device__ __align__(16) float g_c[H];
__device__ __align__(16) float g_u[H];        // W_att[:, :H] @ h + b_att
__device__ __align__(16) float g_scores[S];
__device__ __align__(16) float g_w[S];
__device__ __align__(16) float g_context[E];
__device__ __align__(16) float g_xt[H];
__device__ __align__(16) float g_lse[2];

__device__ __forceinline__ float sigf(float x) { return 1.0f / (1.0f + expf(-x)); }

__device__ __forceinline__ float warp_sum(float s) {
#pragma unroll
    for (int o = 16; o; o >>= 1) s += __shfl_xor_sync(0xFFFFFFFFu, s, o);
    return s;
}

__device__ __forceinline__ uint32_t f2tf(float x) {
    uint32_t r;
    asm("cvt.rna.tf32.f32 %0, %1;" : "=r"(r) : "f"(x));
    return r;
}

__device__ __forceinline__ void mma_tf32(float* c, const uint32_t* a, uint32_t b0, uint32_t b1) {
    asm volatile(
        "mma.sync.aligned.m16n8k8.row.col.f32.tf32.tf32.f32 "
        "{%0,%1,%2,%3}, {%4,%5,%6,%7}, {%8,%9}, {%0,%1,%2,%3};\n"
        : "+f"(c[0]), "+f"(c[1]), "+f"(c[2]), "+f"(c[3])
        : "r"(a[0]), "r"(a[1]), "r"(a[2]), "r"(a[3]), "r"(b0), "r"(b1));
}

// ---------------- K1: LSTM gates matvec ----------------
__global__ void k_gates(const float* __restrict__ W_ih, const float* __restrict__ b_ih,
                        const float* __restrict__ W_hh, const float* __restrict__ b_hh,
                        const float* __restrict__ last_ctx, const float* __restrict__ emb,
                        const int* __restrict__ word, const float* __restrict__ h0) {
    int r    = blockIdx.x * 8 + (threadIdx.x >> 5);
    int lane = threadIdx.x & 31;
    const float4* xe4 = (const float4*)(emb + (size_t)word[0] * E);
    const float4* lc4 = (const float4*)last_ctx;
    const float4* h04 = (const float4*)h0;
    const float4* wi4 = (const float4*)(W_ih + (size_t)r * (E + H));
    const float4* wh4 = (const float4*)(W_hh + (size_t)r * H);

    float s = 0.f;
#pragma unroll
    for (int q = 0; q < 8; q++) {
        int k = lane + 32 * q;
        float4 a = wi4[k];       float4 b = lc4[k];
        s += a.x * b.x + a.y * b.y + a.z * b.z + a.w * b.w;
        float4 a2 = wi4[256 + k]; float4 b2 = xe4[k];
        s += a2.x * b2.x + a2.y * b2.y + a2.z * b2.z + a2.w * b2.w;
        float4 a3 = wh4[k];      float4 b3 = h04[k];
        s += a3.x * b3.x + a3.y * b3.y + a3.z * b3.z + a3.w * b3.w;
    }
    s = warp_sum(s);
    if (lane == 0) g_gates[r] = s + b_ih[r] + b_hh[r];
}

// ---------------- K2: LSTM cell elementwise + scratch zeroing ----------------
__global__ void k_cell(const float* __restrict__ c0, float* __restrict__ out) {
    int t = threadIdx.x;
    float ig = sigf(g_gates[t]);
    float fg = sigf(g_gates[H + t]);
    float gg = tanhf(g_gates[2 * H + t]);
    float og = sigf(g_gates[3 * H + t]);
    float c  = fg * c0[t] + ig * gg;
    float h  = og * tanhf(c);
    g_h[t] = h;
    g_c[t] = c;
    out[V + t]     = h;
    out[V + H + t] = c;
    g_context[t] = 0.f;
    g_scores[t] = 0.f;
    g_scores[H + t] = 0.f;
}

// ---------------- K2b: u = W_att[:, :H] @ h + b_att ----------------
__global__ void k_u(const float* __restrict__ W_att, const float* __restrict__ b_att) {
    int r    = blockIdx.x * 8 + (threadIdx.x >> 5);
    int lane = threadIdx.x & 31;
    const float4* wa4 = (const float4*)(W_att + (size_t)r * (H + E));
    const float4* h4  = (const float4*)g_h;
    float s = 0.f;
#pragma unroll
    for (int q = 0; q < 8; q++) {
        int k = lane + 32 * q;
        float4 a = wa4[k]; float4 b = h4[k];
        s += a.x * b.x + a.y * b.y + a.z * b.z + a.w * b.w;
    }
    s = warp_sum(s);
    if (lane == 0) g_u[r] = s + b_att[r];
}

// ---------------- K3: attention GEMM (tf32 tensor cores) + fused tanh/v reduction ----------------
// C[s,h] = sum_k enc[s,k] * W_att[h, H+k];  scores[s] += sum_h v[h]*tanh(C+u[h])
// Tile 64(s) x 128(h), K-chunk 32, 256 threads, 2 CTAs/SM. grid (32, 8) = 256 CTAs.
#define BM 64
#define BN 128
#define BKC 32
#define PADK 36

__global__ void __launch_bounds__(256, 2)
k_att_tc(const float* __restrict__ enc, const float* __restrict__ W_att,
         const float* __restrict__ v) {
    __shared__ uint32_t As[BM][PADK];   // tf32 bits, [s_local][k]
    __shared__ uint32_t Bs[BN][PADK];   // tf32 bits, [h_local][k]
    __shared__ float sacc[BM];

    int tid  = threadIdx.x;
    int wid  = tid >> 5;
    int lane = tid & 31;
    int warp_m = wid >> 2;      // 0..1  (32 s-rows each)
    int warp_n = wid & 3;       // 0..3  (32 h-cols each)
    int gid  = lane >> 2;       // 0..7
    int tid4 = lane & 3;        // 0..3
    int s0 = blockIdx.x * BM;
    int h0 = blockIdx.y * BN;

    float acc[2][4][4];
#pragma unroll
    for (int mt = 0; mt < 2; mt++)
#pragma unroll
        for (int nt = 0; nt < 4; nt++)
#pragma unroll
            for (int r = 0; r < 4; r++) acc[mt][nt][r] = 0.f;

    // staging registers for global->smem double buffering
    // A: 64 rows * 8 float4 = 512 -> 2 per thread;  B: 128 rows * 8 = 1024 -> 4 per thread
    float4 stA[2], stB[4];
    int rA[2], cA[2], rB[4], cB[4];
#pragma unroll
    for (int i = 0; i < 2; i++) {
        int f = tid + 256 * i;
        rA[i] = f >> 3;  cA[i] = f & 7;
    }
#pragma unroll
    for (int i = 0; i < 4; i++) {
        int f = tid + 256 * i;
        rB[i] = f >> 3;  cB[i] = f & 7;
    }

    // load chunk 0
#pragma unroll
    for (int i = 0; i < 2; i++)
        stA[i] = *(const float4*)(enc   + (size_t)(s0 + rA[i]) * E + cA[i] * 4);
#pragma unroll
    for (int i = 0; i < 4; i++)
        stB[i] = *(const float4*)(W_att + (size_t)(h0 + rB[i]) * (H + E) + H + cB[i] * 4);

    for (int kc = 0; kc < E / BKC; kc++) {
        __syncthreads();   // previous compute done reading smem
#pragma unroll
        for (int i = 0; i < 2; i++) {
            uint4 ua = make_uint4(f2tf(stA[i].x), f2tf(stA[i].y), f2tf(stA[i].z), f2tf(stA[i].w));
            *(uint4*)&As[rA[i]][cA[i] * 4] = ua;
        }
#pragma unroll
        for (int i = 0; i < 4; i++) {
            uint4 ub = make_uint4(f2tf(stB[i].x), f2tf(stB[i].y), f2tf(stB[i].z), f2tf(stB[i].w));
            *(uint4*)&Bs[rB[i]][cB[i] * 4] = ub;
        }
        __syncthreads();

        if (kc + 1 < E / BKC) {
            int k0 = (kc + 1) * BKC;
#pragma unroll
            for (int i = 0; i < 2; i++)
                stA[i] = *(const float4*)(enc   + (size_t)(s0 + rA[i]) * E + k0 + cA[i] * 4);
#pragma unroll
            for (int i = 0; i < 4; i++)
                stB[i] = *(const float4*)(W_att + (size_t)(h0 + rB[i]) * (H + E) + H + k0 + cB[i] * 4);
        }

#pragma unroll
        for (int ks = 0; ks < BKC / 8; ks++) {
            int kb = ks * 8;
            uint32_t af[2][4];
#pragma unroll
            for (int mt = 0; mt < 2; mt++) {
                int row = warp_m * 32 + mt * 16 + gid;
                af[mt][0] = As[row][kb + tid4];
                af[mt][1] = As[row + 8][kb + tid4];
                af[mt][2] = As[row][kb + tid4 + 4];
                af[mt][3] = As[row + 8][kb + tid4 + 4];
            }
#pragma unroll
            for (int nt = 0; nt < 4; nt++) {
                int col = warp_n * 32 + nt * 8 + gid;
                uint32_t b0 = Bs[col][kb + tid4];
                uint32_t b1 = Bs[col][kb + tid4 + 4];
#pragma unroll
                for (int mt = 0; mt < 2; mt++)
                    mma_tf32(acc[mt][nt], af[mt], b0, b1);
            }
        }
    }

    // ---- epilogue: scores[s] += sum_h v[h]*tanh(C[s,h]+u[h]) ----
    __syncthreads();
    if (tid < BM) sacc[tid] = 0.f;
    __syncthreads();

    float uu[4][2], vv[4][2];
#pragma unroll
    for (int nt = 0; nt < 4; nt++) {
        int h = h0 + warp_n * 32 + nt * 8 + 2 * tid4;
        uu[nt][0] = g_u[h];     uu[nt][1] = g_u[h + 1];
        vv[nt][0] = v[h];       vv[nt][1] = v[h + 1];
    }
#pragma unroll
    for (int mt = 0; mt < 2; mt++) {
        float r0 = 0.f, r1 = 0.f;
#pragma unroll
        for (int nt = 0; nt < 4; nt++) {
            r0 += vv[nt][0] * tanhf(acc[mt][nt][0] + uu[nt][0])
                + vv[nt][1] * tanhf(acc[mt][nt][1] + uu[nt][1]);
            r1 += vv[nt][0] * tanhf(acc[mt][nt][2] + uu[nt][0])
                + vv[nt][1] * tanhf(acc[mt][nt][3] + uu[nt][1]);
        }
        r0 += __shfl_xor_sync(0xFFFFFFFFu, r0, 1);
        r0 += __shfl_xor_sync(0xFFFFFFFFu, r0, 2);
        r1 += __shfl_xor_sync(0xFFFFFFFFu, r1, 1);
        r1 += __shfl_xor_sync(0xFFFFFFFFu, r1, 2);
        if (tid4 == 0) {
            atomicAdd(&sacc[warp_m * 32 + mt * 16 + gid], r0);
            atomicAdd(&sacc[warp_m * 32 + mt * 16 + gid + 8], r1);
        }
    }
    __syncthreads();
    if (tid < BM) atomicAdd(&g_scores[s0 + tid], sacc[tid]);
}

// ---------------- K4: softmax over scores[2048] -> w ----------------
__global__ void k_softmax(float* __restrict__ out) {
    __shared__ float red[256];
    int t = threadIdx.x;
    float m = -1e30f;
    for (int s = t; s < S; s += 256) m = fmaxf(m, g_scores[s]);
    red[t] = m; __syncthreads();
    for (int o = 128; o; o >>= 1) { if (t < o) red[t] = fmaxf(red[t], red[t + o]); __syncthreads(); }
    m = red[0]; __syncthreads();
    float sum = 0.f;
    for (int s = t; s < S; s += 256) sum += expf(g_scores[s] - m);
    red[t] = sum; __syncthreads();
    for (int o = 128; o; o >>= 1) { if (t < o) red[t] += red[t + o]; __syncthreads(); }
    float tot = red[0];
    float inv = 1.0f / tot;
    for (int s = t; s < S; s += 256) {
        float w = expf(g_scores[s] - m) * inv;
        g_w[s] = w;
        out[V + 3 * H + s] = w;
    }
}

// ---------------- K5: context = w @ enc ----------------
// grid (E/256=4, S/64=32) x 256 threads, atomicAdd into g_context
__global__ void k_context(const float* __restrict__ enc) {
    int e = blockIdx.x * 256 + threadIdx.x;
    int s0 = blockIdx.y * 64;
    float acc = 0.f;
#pragma unroll 4
    for (int s = s0; s < s0 + 64; s++)
        acc += g_w[s] * enc[(size_t)s * E + e];
    atomicAdd(&g_context[e], acc);
}

// ---------------- K6: x_t = tanh(W_ah @ [context, h] + b_ah) ----------------
__global__ void k_xt(const float* __restrict__ W_ah, const float* __restrict__ b_ah,
                     float* __restrict__ out) {
    int r    = blockIdx.x * 8 + (threadIdx.x >> 5);
    int lane = threadIdx.x & 31;
    const float4* wa4 = (const float4*)(W_ah + (size_t)r * (E + H));
    const float4* c4  = (const float4*)g_context;
    const float4* h4  = (const float4*)g_h;
    float s = 0.f;
#pragma unroll
    for (int q = 0; q < 8; q++) {
        int k = lane + 32 * q;
        float4 a = wa4[k];        float4 b = c4[k];
        s += a.x * b.x + a.y * b.y + a.z * b.z + a.w * b.w;
        float4 a2 = wa4[256 + k]; float4 b2 = h4[k];
        s += a2.x * b2.x + a2.y * b2.y + a2.z * b2.z + a2.w * b2.w;
    }
    s = warp_sum(s);
    if (lane == 0) {
        float xt = tanhf(s + b_ah[r]);
        g_xt[r] = xt;
        out[V + 2 * H + r] = xt;
    }
}

// ---------------- K7: logits = W_out @ x_t + b_out ----------------
__global__ void k_logits(const float* __restrict__ W_out, const float* __restrict__ b_out,
                         float* __restrict__ out) {
    int r    = blockIdx.x * 8 + (threadIdx.x >> 5);
    int lane = threadIdx.x & 31;
    const float4* w4 = (const float4*)(W_out + (size_t)r * H);
    const float4* x4 = (const float4*)g_xt;
    float s = 0.f;
#pragma unroll
    for (int q = 0; q < 8; q++) {
        int k = lane + 32 * q;
        float4 a = w4[k]; float4 b = x4[k];
        s += a.x * b.x + a.y * b.y + a.z * b.z + a.w * b.w;
    }
    s = warp_sum(s);
    if (lane == 0) out[r] = s + b_out[r];
}

// ---------------- K8: log-sum-exp over logits (1024 threads for MLP) ----------------
__global__ void k_lse(const float* __restrict__ out) {
    __shared__ float red[1024];
    int t = threadIdx.x;
    float m = -1e30f;
    for (int i = t; i < V; i += 1024) m = fmaxf(m, out[i]);
    red[t] = m; __syncthreads();
    for (int o = 512; o; o >>= 1) { if (t < o) red[t] = fmaxf(red[t], red[t + o]); __syncthreads(); }
    m = red[0]; __syncthreads();
    float sum = 0.f;
    for (int i = t; i < V; i += 1024) sum += expf(out[i] - m);
    red[t] = sum; __syncthreads();
    for (int o = 512; o; o >>= 1) { if (t < o) red[t] += red[t + o]; __syncthreads(); }
    if (t == 0) { g_lse[0] = m; g_lse[1] = logf(red[0]); }
}

// ---------------- K9: out[i] = logit - max - log(sumexp) ----------------
__global__ void k_logsoftmax(float* __restrict__ out) {
    int i = blockIdx.x * 256 + threadIdx.x;
    if (i < V) out[i] = out[i] - g_lse[0] - g_lse[1];
}

// ---------------- launch ----------------
extern "C" void kernel_launch(void* const* d_in, const int* in_sizes, int n_in,
                              void* d_out, int out_size) {
    const float* enc      = (const float*)d_in[0];
    const int*   word     = (const int*)  d_in[1];
    const float* last_ctx = (const float*)d_in[2];
    const float* h0       = (const float*)d_in[3];
    const float* c0       = (const float*)d_in[4];
    const float* emb      = (const float*)d_in[5];
    const float* W_ih     = (const float*)d_in[6];
    const float* b_ih     = (const float*)d_in[7];
    const float* W_hh     = (const float*)d_in[8];
    const float* b_hh     = (const float*)d_in[9];
    const float* W_att    = (const float*)d_in[10];
    const float* b_att    = (const float*)d_in[11];
    const float* v        = (const float*)d_in[12];
    const float* W_ah     = (const float*)d_in[13];
    const float* b_ah     = (const float*)d_in[14];
    const float* W_out    = (const float*)d_in[15];
    const float* b_out    = (const float*)d_in[16];
    float* out = (float*)d_out;

    k_gates<<<512, 256>>>(W_ih, b_ih, W_hh, b_hh, last_ctx, emb, word, h0);
    k_cell<<<1, 1024>>>(c0, out);
    k_u<<<128, 256>>>(W_att, b_att);
    dim3 g3(S / BM, H / BN);
    k_att_tc<<<g3, 256>>>(enc, W_att, v);
    k_softmax<<<1, 256>>>(out);
    dim3 g5(E / 256, S / 64);
    k_context<<<g5, 256>>>(enc);
    k_xt<<<128, 256>>>(W_ah, b_ah, out);
    k_logits<<<V / 8, 256>>>(W_out, b_out, out);
    k_lse<<<1, 1024>>>(out);
    k_logsoftmax<<<(V + 255) / 256, 256>>>(out);
}

// round 6
// speedup vs baseline: 1.9349x; 1.0188x over previous
#include <cuda_runtime.h>
#include <cstdint>

// ---------------- problem constants ----------------
#define S  2048
#define E  1024
#define H  1024
#define V  32000

// ---------------- device scratch (no allocs allowed) ----------------
__device__ __align__(16) float g_gates[4 * H];
__device__ __align__(16) float g_h[H];
__device__ __align__(16) float g_c[H];
__device__ __align__(16) float g_u[H];        // W_att[:, :H] @ h + b_att
__device__ __align__(16) float g_scores[S];
__device__ __align__(16) float g_w[S];
__device__ __align__(16) float g_context[E];
__device__ __align__(16) float g_xt[H];
__device__ __align__(16) float g_lse[2];

__device__ __forceinline__ float sigf(float x) { return 1.0f / (1.0f + expf(-x)); }

__device__ __forceinline__ float warp_sum(float s) {
#pragma unroll
    for (int o = 16; o; o >>= 1) s += __shfl_xor_sync(0xFFFFFFFFu, s, o);
    return s;
}

__device__ __forceinline__ void mma_tf32(float* c, const uint32_t* a, uint32_t b0, uint32_t b1) {
    asm volatile(
        "mma.sync.aligned.m16n8k8.row.col.f32.tf32.tf32.f32 "
        "{%0,%1,%2,%3}, {%4,%5,%6,%7}, {%8,%9}, {%0,%1,%2,%3};\n"
        : "+f"(c[0]), "+f"(c[1]), "+f"(c[2]), "+f"(c[3])
        : "r"(a[0]), "r"(a[1]), "r"(a[2]), "r"(a[3]), "r"(b0), "r"(b1));
}

__device__ __forceinline__ void cp16(uint32_t dst_smem, const void* src) {
    asm volatile("cp.async.cg.shared.global [%0], [%1], 16;\n" :: "r"(dst_smem), "l"(src));
}
__device__ __forceinline__ void cp_commit() {
    asm volatile("cp.async.commit_group;\n");
}
template <int N>
__device__ __forceinline__ void cp_wait() {
    asm volatile("cp.async.wait_group %0;\n" :: "n"(N));
}

// ---------------- K1: LSTM gates matvec ----------------
__global__ void k_gates(const float* __restrict__ W_ih, const float* __restrict__ b_ih,
                        const float* __restrict__ W_hh, const float* __restrict__ b_hh,
                        const float* __restrict__ last_ctx, const float* __restrict__ emb,
                        const int* __restrict__ word, const float* __restrict__ h0) {
    int r    = blockIdx.x * 8 + (threadIdx.x >> 5);
    int lane = threadIdx.x & 31;
    const float4* xe4 = (const float4*)(emb + (size_t)word[0] * E);
    const float4* lc4 = (const float4*)last_ctx;
    const float4* h04 = (const float4*)h0;
    const float4* wi4 = (const float4*)(W_ih + (size_t)r * (E + H));
    const float4* wh4 = (const float4*)(W_hh + (size_t)r * H);

    float s = 0.f;
#pragma unroll
    for (int q = 0; q < 8; q++) {
        int k = lane + 32 * q;
        float4 a = wi4[k];       float4 b = lc4[k];
        s += a.x * b.x + a.y * b.y + a.z * b.z + a.w * b.w;
        float4 a2 = wi4[256 + k]; float4 b2 = xe4[k];
        s += a2.x * b2.x + a2.y * b2.y + a2.z * b2.z + a2.w * b2.w;
        float4 a3 = wh4[k];      float4 b3 = h04[k];
        s += a3.x * b3.x + a3.y * b3.y + a3.z * b3.z + a3.w * b3.w;
    }
    s = warp_sum(s);
    if (lane == 0) g_gates[r] = s + b_ih[r] + b_hh[r];
}

// ---------------- K2: LSTM cell elementwise + scratch zeroing ----------------
__global__ void k_cell(const float* __restrict__ c0, float* __restrict__ out) {
    int t = threadIdx.x;
    float ig = sigf(g_gates[t]);
    float fg = sigf(g_gates[H + t]);
    float gg = tanhf(g_gates[2 * H + t]);
    float og = sigf(g_gates[3 * H + t]);
    float c  = fg * c0[t] + ig * gg;
    float h  = og * tanhf(c);
    g_h[t] = h;
    g_c[t] = c;
    out[V + t]     = h;
    out[V + H + t] = c;
    g_context[t] = 0.f;
    g_scores[t] = 0.f;
    g_scores[H + t] = 0.f;
}

// ---------------- K2b: u = W_att[:, :H] @ h + b_att ----------------
__global__ void k_u(const float* __restrict__ W_att, const float* __restrict__ b_att) {
    int r    = blockIdx.x * 8 + (threadIdx.x >> 5);
    int lane = threadIdx.x & 31;
    const float4* wa4 = (const float4*)(W_att + (size_t)r * (H + E));
    const float4* h4  = (const float4*)g_h;
    float s = 0.f;
#pragma unroll
    for (int q = 0; q < 8; q++) {
        int k = lane + 32 * q;
        float4 a = wa4[k]; float4 b = h4[k];
        s += a.x * b.x + a.y * b.y + a.z * b.z + a.w * b.w;
    }
    s = warp_sum(s);
    if (lane == 0) g_u[r] = s + b_att[r];
}

// ---------------- K3: attention GEMM (tf32 tensor cores, cp.async 4-stage) ----------------
// C[s,h] = sum_k enc[s,k] * W_att[h, H+k];  scores[s] += sum_h v[h]*tanh(C+u[h])
// Tile 64(s) x 128(h), K-chunk 32, 4 pipeline stages, 1 barrier/chunk.
#define BM 64
#define BN 128
#define BKC 32
#define PADK 36
#define NSTAGE 4
#define NKC (E / BKC)
#define STAGE_FLOATS ((BM + BN) * PADK)           // 6912 floats = 27648 B
#define ATT_SMEM_BYTES (NSTAGE * STAGE_FLOATS * 4)  // 110592 B

__global__ void __launch_bounds__(256, 2)
k_att_tc(const float* __restrict__ enc, const float* __restrict__ W_att,
         const float* __restrict__ v) {
    extern __shared__ float smem_dyn[];
    __shared__ float sacc[BM];

    int tid  = threadIdx.x;
    int wid  = tid >> 5;
    int lane = tid & 31;
    int warp_m = wid >> 2;      // 0..1  (32 s-rows each)
    int warp_n = wid & 3;       // 0..3  (32 h-cols each)
    int gid  = lane >> 2;       // 0..7
    int tid4 = lane & 3;        // 0..3
    int s0 = blockIdx.x * BM;
    int h0 = blockIdx.y * BN;

    uint32_t smem_u32;
    {
        uint64_t tmp;
        asm("cvta.to.shared.u64 %0, %1;" : "=l"(tmp) : "l"(smem_dyn));
        smem_u32 = (uint32_t)tmp;
    }

    float acc[2][4][4];
#pragma unroll
    for (int mt = 0; mt < 2; mt++)
#pragma unroll
        for (int nt = 0; nt < 4; nt++)
#pragma unroll
            for (int r = 0; r < 4; r++) acc[mt][nt][r] = 0.f;

    // per-thread copy assignments
    // A: 64 rows * 8 chunks(16B) = 512 -> 2/thread;  B: 128 rows * 8 = 1024 -> 4/thread
    int rA[2], cA[2], rB[4], cB[4];
#pragma unroll
    for (int i = 0; i < 2; i++) { int f = tid + 256 * i; rA[i] = f >> 3; cA[i] = f & 7; }
#pragma unroll
    for (int i = 0; i < 4; i++) { int f = tid + 256 * i; rB[i] = f >> 3; cB[i] = f & 7; }

    const float* encp = enc   + (size_t)s0 * E;
    const float* wap  = W_att + (size_t)h0 * (H + E) + H;

#define ISSUE(kc_) do {                                                             \
        int st_ = (kc_) & (NSTAGE - 1);                                             \
        uint32_t abase_ = smem_u32 + st_ * (STAGE_FLOATS * 4);                      \
        uint32_t bbase_ = abase_ + BM * PADK * 4;                                   \
        int kofs_ = (kc_) * BKC;                                                    \
        _Pragma("unroll")                                                           \
        for (int i = 0; i < 2; i++)                                                 \
            cp16(abase_ + (rA[i] * PADK + cA[i] * 4) * 4,                           \
                 encp + (size_t)rA[i] * E + kofs_ + cA[i] * 4);                     \
        _Pragma("unroll")                                                           \
        for (int i = 0; i < 4; i++)                                                 \
            cp16(bbase_ + (rB[i] * PADK + cB[i] * 4) * 4,                           \
                 wap + (size_t)rB[i] * (H + E) + kofs_ + cB[i] * 4);                \
        cp_commit();                                                                \
    } while (0)

    ISSUE(0); ISSUE(1); ISSUE(2);

    for (int kc = 0; kc < NKC; kc++) {
        cp_wait<2>();
        __syncthreads();
        if (kc + 3 < NKC) ISSUE(kc + 3);

        int st = kc & (NSTAGE - 1);
        const uint32_t* As_s = (const uint32_t*)(smem_dyn + st * STAGE_FLOATS);
        const uint32_t* Bs_s = As_s + BM * PADK;

#pragma unroll
        for (int ks = 0; ks < BKC / 8; ks++) {
            int kb = ks * 8;
            uint32_t af[2][4];
#pragma unroll
            for (int mt = 0; mt < 2; mt++) {
                int row = warp_m * 32 + mt * 16 + gid;
                af[mt][0] = As_s[row * PADK + kb + tid4];
                af[mt][1] = As_s[(row + 8) * PADK + kb + tid4];
                af[mt][2] = As_s[row * PADK + kb + tid4 + 4];
                af[mt][3] = As_s[(row + 8) * PADK + kb + tid4 + 4];
            }
#pragma unroll
            for (int nt = 0; nt < 4; nt++) {
                int col = warp_n * 32 + nt * 8 + gid;
                uint32_t b0 = Bs_s[col * PADK + kb + tid4];
                uint32_t b1 = Bs_s[col * PADK + kb + tid4 + 4];
#pragma unroll
                for (int mt = 0; mt < 2; mt++)
                    mma_tf32(acc[mt][nt], af[mt], b0, b1);
            }
        }
    }
#undef ISSUE

    // ---- epilogue: scores[s] += sum_h v[h]*tanh(C[s,h]+u[h]) ----
    __syncthreads();
    if (tid < BM) sacc[tid] = 0.f;
    __syncthreads();

    float uu[4][2], vv[4][2];
#pragma unroll
    for (int nt = 0; nt < 4; nt++) {
        int h = h0 + warp_n * 32 + nt * 8 + 2 * tid4;
        uu[nt][0] = g_u[h];     uu[nt][1] = g_u[h + 1];
        vv[nt][0] = v[h];       vv[nt][1] = v[h + 1];
    }
#pragma unroll
    for (int mt = 0; mt < 2; mt++) {
        float r0 = 0.f, r1 = 0.f;
#pragma unroll
        for (int nt = 0; nt < 4; nt++) {
            r0 += vv[nt][0] * tanhf(acc[mt][nt][0] + uu[nt][0])
                + vv[nt][1] * tanhf(acc[mt][nt][1] + uu[nt][1]);
            r1 += vv[nt][0] * tanhf(acc[mt][nt][2] + uu[nt][0])
                + vv[nt][1] * tanhf(acc[mt][nt][3] + uu[nt][1]);
        }
        r0 += __shfl_xor_sync(0xFFFFFFFFu, r0, 1);
        r0 += __shfl_xor_sync(0xFFFFFFFFu, r0, 2);
        r1 += __shfl_xor_sync(0xFFFFFFFFu, r1, 1);
        r1 += __shfl_xor_sync(0xFFFFFFFFu, r1, 2);
        if (tid4 == 0) {
            atomicAdd(&sacc[warp_m * 32 + mt * 16 + gid], r0);
            atomicAdd(&sacc[warp_m * 32 + mt * 16 + gid + 8], r1);
        }
    }
    __syncthreads();
    if (tid < BM) atomicAdd(&g_scores[s0 + tid], sacc[tid]);
}

// ---------------- K4: softmax over scores[2048] -> w ----------------
__global__ void k_softmax(float* __restrict__ out) {
    __shared__ float red[256];
    int t = threadIdx.x;
    float m = -1e30f;
    for (int s = t; s < S; s += 256) m = fmaxf(m, g_scores[s]);
    red[t] = m; __syncthreads();
    for (int o = 128; o; o >>= 1) { if (t < o) red[t] = fmaxf(red[t], red[t + o]); __syncthreads(); }
    m = red[0]; __syncthreads();
    float sum = 0.f;
    for (int s = t; s < S; s += 256) sum += expf(g_scores[s] - m);
    red[t] = sum; __syncthreads();
    for (int o = 128; o; o >>= 1) { if (t < o) red[t] += red[t + o]; __syncthreads(); }
    float tot = red[0];
    float inv = 1.0f / tot;
    for (int s = t; s < S; s += 256) {
        float w = expf(g_scores[s] - m) * inv;
        g_w[s] = w;
        out[V + 3 * H + s] = w;
    }
}

// ---------------- K5: context = w @ enc ----------------
__global__ void k_context(const float* __restrict__ enc) {
    int e = blockIdx.x * 256 + threadIdx.x;
    int s0 = blockIdx.y * 64;
    float acc = 0.f;
#pragma unroll 4
    for (int s = s0; s < s0 + 64; s++)
        acc += g_w[s] * enc[(size_t)s * E + e];
    atomicAdd(&g_context[e], acc);
}

// ---------------- K6: x_t = tanh(W_ah @ [context, h] + b_ah) ----------------
__global__ void k_xt(const float* __restrict__ W_ah, const float* __restrict__ b_ah,
                     float* __restrict__ out) {
    int r    = blockIdx.x * 8 + (threadIdx.x >> 5);
    int lane = threadIdx.x & 31;
    const float4* wa4 = (const float4*)(W_ah + (size_t)r * (E + H));
    const float4* c4  = (const float4*)g_context;
    const float4* h4  = (const float4*)g_h;
    float s = 0.f;
#pragma unroll
    for (int q = 0; q < 8; q++) {
        int k = lane + 32 * q;
        float4 a = wa4[k];        float4 b = c4[k];
        s += a.x * b.x + a.y * b.y + a.z * b.z + a.w * b.w;
        float4 a2 = wa4[256 + k]; float4 b2 = h4[k];
        s += a2.x * b2.x + a2.y * b2.y + a2.z * b2.z + a2.w * b2.w;
    }
    s = warp_sum(s);
    if (lane == 0) {
        float xt = tanhf(s + b_ah[r]);
        g_xt[r] = xt;
        out[V + 2 * H + r] = xt;
    }
}

// ---------------- K7: logits = W_out @ x_t + b_out ----------------
__global__ void k_logits(const float* __restrict__ W_out, const float* __restrict__ b_out,
                         float* __restrict__ out) {
    int r    = blockIdx.x * 8 + (threadIdx.x >> 5);
    int lane = threadIdx.x & 31;
    const float4* w4 = (const float4*)(W_out + (size_t)r * H);
    const float4* x4 = (const float4*)g_xt;
    float s = 0.f;
#pragma unroll
    for (int q = 0; q < 8; q++) {
        int k = lane + 32 * q;
        float4 a = w4[k]; float4 b = x4[k];
        s += a.x * b.x + a.y * b.y + a.z * b.z + a.w * b.w;
    }
    s = warp_sum(s);
    if (lane == 0) out[r] = s + b_out[r];
}

// ---------------- K8: log-sum-exp over logits (1024 threads for MLP) ----------------
__global__ void k_lse(const float* __restrict__ out) {
    __shared__ float red[1024];
    int t = threadIdx.x;
    float m = -1e30f;
    for (int i = t; i < V; i += 1024) m = fmaxf(m, out[i]);
    red[t] = m; __syncthreads();
    for (int o = 512; o; o >>= 1) { if (t < o) red[t] = fmaxf(red[t], red[t + o]); __syncthreads(); }
    m = red[0]; __syncthreads();
    float sum = 0.f;
    for (int i = t; i < V; i += 1024) sum += expf(out[i] - m);
    red[t] = sum; __syncthreads();
    for (int o = 512; o; o >>= 1) { if (t < o) red[t] += red[t + o]; __syncthreads(); }
    if (t == 0) { g_lse[0] = m; g_lse[1] = logf(red[0]); }
}

// ---------------- K9: out[i] = logit - max - log(sumexp) ----------------
__global__ void k_logsoftmax(float* __restrict__ out) {
    int i = blockIdx.x * 256 + threadIdx.x;
    if (i < V) out[i] = out[i] - g_lse[0] - g_lse[1];
}

// ---------------- launch ----------------
extern "C" void kernel_launch(void* const* d_in, const int* in_sizes, int n_in,
                              void* d_out, int out_size) {
    const float* enc      = (const float*)d_in[0];
    const int*   word     = (const int*)  d_in[1];
    const float* last_ctx = (const float*)d_in[2];
    const float* h0       = (const float*)d_in[3];
    const float* c0       = (const float*)d_in[4];
    const float* emb      = (const float*)d_in[5];
    const float* W_ih     = (const float*)d_in[6];
    const float* b_ih     = (const float*)d_in[7];
    const float* W_hh     = (const float*)d_in[8];
    const float* b_hh     = (const float*)d_in[9];
    const float* W_att    = (const float*)d_in[10];
    const float* b_att    = (const float*)d_in[11];
    const float* v        = (const float*)d_in[12];
    const float* W_ah     = (const float*)d_in[13];
    const float* b_ah     = (const float*)d_in[14];
    const float* W_out    = (const float*)d_in[15];
    const float* b_out    = (const float*)d_in[16];
    float* out = (float*)d_out;

    cudaFuncSetAttribute(k_att_tc, cudaFuncAttributeMaxDynamicSharedMemorySize, ATT_SMEM_BYTES);

    k_gates<<<512, 256>>>(W_ih, b_ih, W_hh, b_hh, last_ctx, emb, word, h0);
    k_cell<<<1, 1024>>>(c0, out);
    k_u<<<128, 256>>>(W_att, b_att);
    dim3 g3(S / BM, H / BN);
    k_att_tc<<<g3, 256, ATT_SMEM_BYTES>>>(enc, W_att, v);
    k_softmax<<<1, 256>>>(out);
    dim3 g5(E / 256, S / 64);
    k_context<<<g5, 256>>>(enc);
    k_xt<<<128, 256>>>(W_ah, b_ah, out);
    k_logits<<<V / 8, 256>>>(W_out, b_out, out);
    k_lse<<<1, 1024>>>(out);
    k_logsoftmax<<<(V + 255) / 256, 256>>>(out);
}

// round 8
// speedup vs baseline: 2.0159x; 1.0419x over previous
#include <cuda_runtime.h>
#include <cstdint>

// ---------------- problem constants ----------------
#define S  2048
#define E  1024
#define H  1024
#define V  32000
#define NLOGB 4000   // k_logits blocks

// ---------------- device scratch (no allocs allowed) ----------------
__device__ __align__(16) float g_gates[4 * H];
__device__ __align__(16) float g_h[H];
__device__ __align__(16) float g_u[H];        // W_att[:, :H] @ h + b_att
__device__ __align__(16) float g_scores[S];
__device__ __align__(16) float g_context[E];
__device__ __align__(16) float g_xt[H];
__device__ __align__(16) float g_C[(size_t)S * H];   // attention GEMM output (8 MB)
__device__ __align__(16) float g_lp[NLOGB];          // per-block exp-sum partials

__device__ __forceinline__ float sigf(float x) { return 1.0f / (1.0f + expf(-x)); }

__device__ __forceinline__ float warp_sum(float s) {
#pragma unroll
    for (int o = 16; o; o >>= 1) s += __shfl_xor_sync(0xFFFFFFFFu, s, o);
    return s;
}

__device__ __forceinline__ void mma_tf32(float* c, const uint32_t* a, uint32_t b0, uint32_t b1) {
    asm volatile(
        "mma.sync.aligned.m16n8k8.row.col.f32.tf32.tf32.f32 "
        "{%0,%1,%2,%3}, {%4,%5,%6,%7}, {%8,%9}, {%0,%1,%2,%3};\n"
        : "+f"(c[0]), "+f"(c[1]), "+f"(c[2]), "+f"(c[3])
        : "r"(a[0]), "r"(a[1]), "r"(a[2]), "r"(a[3]), "r"(b0), "r"(b1));
}

__device__ __forceinline__ void cp16(uint32_t dst_smem, const void* src) {
    asm volatile("cp.async.cg.shared.global [%0], [%1], 16;\n" :: "r"(dst_smem), "l"(src));
}
__device__ __forceinline__ void cp_commit() {
    asm volatile("cp.async.commit_group;\n");
}
template <int N>
__device__ __forceinline__ void cp_wait() {
    asm volatile("cp.async.wait_group %0;\n" :: "n"(N));
}

// ---------------- K1: LSTM gates matvec (side stream) ----------------
__global__ void k_gates(const float* __restrict__ W_ih, const float* __restrict__ b_ih,
                        const float* __restrict__ W_hh, const float* __restrict__ b_hh,
                        const float* __restrict__ last_ctx, const float* __restrict__ emb,
                        const int* __restrict__ word, const float* __restrict__ h0) {
    int r    = blockIdx.x * 8 + (threadIdx.x >> 5);
    int lane = threadIdx.x & 31;
    const float4* xe4 = (const float4*)(emb + (size_t)word[0] * E);
    const float4* lc4 = (const float4*)last_ctx;
    const float4* h04 = (const float4*)h0;
    const float4* wi4 = (const float4*)(W_ih + (size_t)r * (E + H));
    const float4* wh4 = (const float4*)(W_hh + (size_t)r * H);

    float s = 0.f;
#pragma unroll
    for (int q = 0; q < 8; q++) {
        int k = lane + 32 * q;
        float4 a = wi4[k];       float4 b = lc4[k];
        s += a.x * b.x + a.y * b.y + a.z * b.z + a.w * b.w;
        float4 a2 = wi4[256 + k]; float4 b2 = xe4[k];
        s += a2.x * b2.x + a2.y * b2.y + a2.z * b2.z + a2.w * b2.w;
        float4 a3 = wh4[k];      float4 b3 = h04[k];
        s += a3.x * b3.x + a3.y * b3.y + a3.z * b3.z + a3.w * b3.w;
    }
    s = warp_sum(s);
    if (lane == 0) g_gates[r] = s + b_ih[r] + b_hh[r];
}

// ---------------- K2: fused LSTM cell + u = W_att[:,:H]@h + b_att (side stream) ----
// grid 128 blocks x 256 threads; every block recomputes h into smem, then 8 u-rows.
__global__ void k_cell_u(const float* __restrict__ c0, const float* __restrict__ W_att,
                         const float* __restrict__ b_att, float* __restrict__ out) {
    __shared__ float sh[H];
    int tid  = threadIdx.x;
    int wid  = tid >> 5;
    int lane = tid & 31;

#pragma unroll
    for (int j = 0; j < 4; j++) {
        int t = tid + 256 * j;
        float ig = sigf(g_gates[t]);
        float fg = sigf(g_gates[H + t]);
        float gg = tanhf(g_gates[2 * H + t]);
        float og = sigf(g_gates[3 * H + t]);
        float c  = fg * c0[t] + ig * gg;
        float h  = og * tanhf(c);
        sh[t] = h;
        if (blockIdx.x == 0) {
            g_h[t] = h;
            out[V + t]     = h;
            out[V + H + t] = c;
            g_context[t]   = 0.f;
        }
    }
    __syncthreads();

    int r = blockIdx.x * 8 + wid;
    const float4* wa4 = (const float4*)(W_att + (size_t)r * (H + E));
    const float4* h4  = (const float4*)sh;
    float s = 0.f;
#pragma unroll
    for (int q = 0; q < 8; q++) {
        int k = lane + 32 * q;
        float4 a = wa4[k]; float4 b = h4[k];
        s += a.x * b.x + a.y * b.y + a.z * b.z + a.w * b.w;
    }
    s = warp_sum(s);
    if (lane == 0) g_u[r] = s + b_att[r];
}

// ---------------- K3: attention GEMM (tf32 mma.sync, cp.async 4-stage) ----------------
// C[s,h] = sum_k enc[s,k] * W_att[h, H+k]  -> g_C   (no epilogue; no u dependency)
#define BM 64
#define BN 128
#define BKC 32
#define PADK 36
#define NSTAGE 4
#define NKC (E / BKC)
#define STAGE_FLOATS ((BM + BN) * PADK)
#define ATT_SMEM_BYTES (NSTAGE * STAGE_FLOATS * 4)

__global__ void __launch_bounds__(256, 2)
k_att_gemm(const float* __restrict__ enc, const float* __restrict__ W_att) {
    extern __shared__ float smem_dyn[];

    int tid  = threadIdx.x;
    int wid  = tid >> 5;
    int lane = tid & 31;
    int warp_m = wid >> 2;
    int warp_n = wid & 3;
    int gid  = lane >> 2;
    int tid4 = lane & 3;
    int s0 = blockIdx.x * BM;
    int h0 = blockIdx.y * BN;

    uint32_t smem_u32;
    {
        uint64_t tmp;
        asm("cvta.to.shared.u64 %0, %1;" : "=l"(tmp) : "l"(smem_dyn));
        smem_u32 = (uint32_t)tmp;
    }

    float acc[2][4][4];
#pragma unroll
    for (int mt = 0; mt < 2; mt++)
#pragma unroll
        for (int nt = 0; nt < 4; nt++)
#pragma unroll
            for (int r = 0; r < 4; r++) acc[mt][nt][r] = 0.f;

    int rA[2], cA[2], rB[4], cB[4];
#pragma unroll
    for (int i = 0; i < 2; i++) { int f = tid + 256 * i; rA[i] = f >> 3; cA[i] = f & 7; }
#pragma unroll
    for (int i = 0; i < 4; i++) { int f = tid + 256 * i; rB[i] = f >> 3; cB[i] = f & 7; }

    const float* encp = enc   + (size_t)s0 * E;
    const float* wap  = W_att + (size_t)h0 * (H + E) + H;

#define ISSUE(kc_) do {                                                             \
        int st_ = (kc_) & (NSTAGE - 1);                                             \
        uint32_t abase_ = smem_u32 + st_ * (STAGE_FLOATS * 4);                      \
        uint32_t bbase_ = abase_ + BM * PADK * 4;                                   \
        int kofs_ = (kc_) * BKC;                                                    \
        _Pragma("unroll")                                                           \
        for (int i = 0; i < 2; i++)                                                 \
            cp16(abase_ + (rA[i] * PADK + cA[i] * 4) * 4,                           \
                 encp + (size_t)rA[i] * E + kofs_ + cA[i] * 4);                     \
        _Pragma("unroll")                                                           \
        for (int i = 0; i < 4; i++)                                                 \
            cp16(bbase_ + (rB[i] * PADK + cB[i] * 4) * 4,                           \
                 wap + (size_t)rB[i] * (H + E) + kofs_ + cB[i] * 4);                \
        cp_commit();                                                                \
    } while (0)

    ISSUE(0); ISSUE(1); ISSUE(2);

    for (int kc = 0; kc < NKC; kc++) {
        cp_wait<2>();
        __syncthreads();
        if (kc + 3 < NKC) ISSUE(kc + 3);

        int st = kc & (NSTAGE - 1);
        const uint32_t* As_s = (const uint32_t*)(smem_dyn + st * STAGE_FLOATS);
        const uint32_t* Bs_s = As_s + BM * PADK;

#pragma unroll
        for (int ks = 0; ks < BKC / 8; ks++) {
            int kb = ks * 8;
            uint32_t af[2][4];
#pragma unroll
            for (int mt = 0; mt < 2; mt++) {
                int row = warp_m * 32 + mt * 16 + gid;
                af[mt][0] = As_s[row * PADK + kb + tid4];
                af[mt][1] = As_s[(row + 8) * PADK + kb + tid4];
                af[mt][2] = As_s[row * PADK + kb + tid4 + 4];
                af[mt][3] = As_s[(row + 8) * PADK + kb + tid4 + 4];
            }
#pragma unroll
            for (int nt = 0; nt < 4; nt++) {
                int col = warp_n * 32 + nt * 8 + gid;
                uint32_t b0 = Bs_s[col * PADK + kb + tid4];
                uint32_t b1 = Bs_s[col * PADK + kb + tid4 + 4];
#pragma unroll
                for (int mt = 0; mt < 2; mt++)
                    mma_tf32(acc[mt][nt], af[mt], b0, b1);
            }
        }
    }
#undef ISSUE

    // store C tile
#pragma unroll
    for (int mt = 0; mt < 2; mt++) {
        int srow = s0 + warp_m * 32 + mt * 16 + gid;
#pragma unroll
        for (int nt = 0; nt < 4; nt++) {
            int hcol = h0 + warp_n * 32 + nt * 8 + 2 * tid4;
            float2 v0 = make_float2(acc[mt][nt][0], acc[mt][nt][1]);
            float2 v1 = make_float2(acc[mt][nt][2], acc[mt][nt][3]);
            *(float2*)&g_C[(size_t)srow * H + hcol]       = v0;
            *(float2*)&g_C[(size_t)(srow + 8) * H + hcol] = v1;
        }
    }
}

// ---------------- K4: score epilogue: scores[s] = sum_h v[h]*tanh(C[s,h]+u[h]) ----
// grid 2048 blocks x 256 threads (block per s-row, 1 float4 per thread)
__global__ void k_score(const float* __restrict__ v) {
    __shared__ float red[8];
    int tid  = threadIdx.x;
    int wid  = tid >> 5;
    int lane = tid & 31;

    float4 c  = ((const float4*)(g_C + (size_t)blockIdx.x * H))[tid];
    float4 u4 = ((const float4*)g_u)[tid];
    float4 v4 = ((const float4*)v)[tid];
    float p = v4.x * tanhf(c.x + u4.x) + v4.y * tanhf(c.y + u4.y)
            + v4.z * tanhf(c.z + u4.z) + v4.w * tanhf(c.w + u4.w);
    p = warp_sum(p);
    if (lane == 0) red[wid] = p;
    __syncthreads();
    if (tid == 0) {
        float t = 0.f;
#pragma unroll
        for (int i = 0; i < 8; i++) t += red[i];
        g_scores[blockIdx.x] = t;
    }
}

// ---------------- K5: fused softmax + context = softmax(scores) @ enc ----------------
// grid (E/256=4, S/64=32) x 256 threads; each block redundantly reduces scores.
__global__ void k_ctx(const float* __restrict__ enc, float* __restrict__ out) {
    __shared__ float red[256];
    __shared__ float sw[64];
    int tid = threadIdx.x;
    int e   = blockIdx.x * 256 + tid;
    int s0c = blockIdx.y * 64;

    float m = -1e30f;
    for (int s = tid; s < S; s += 256) m = fmaxf(m, g_scores[s]);
    red[tid] = m; __syncthreads();
    for (int o = 128; o; o >>= 1) { if (tid < o) red[tid] = fmaxf(red[tid], red[tid + o]); __syncthreads(); }
    m = red[0]; __syncthreads();
    float sum = 0.f;
    for (int s = tid; s < S; s += 256) sum += expf(g_scores[s] - m);
    red[tid] = sum; __syncthreads();
    for (int o = 128; o; o >>= 1) { if (tid < o) red[tid] += red[tid + o]; __syncthreads(); }
    float inv = 1.0f / red[0];

    if (tid < 64) {
        float w = expf(g_scores[s0c + tid] - m) * inv;
        sw[tid] = w;
        if (blockIdx.x == 0) out[V + 3 * H + s0c + tid] = w;
    }
    __syncthreads();

    float acc = 0.f;
#pragma unroll 4
    for (int s = 0; s < 64; s++)
        acc += sw[s] * enc[(size_t)(s0c + s) * E + e];
    atomicAdd(&g_context[e], acc);
}

// ---------------- K6: x_t = tanh(W_ah @ [context, h] + b_ah) ----------------
__global__ void k_xt(const float* __restrict__ W_ah, const float* __restrict__ b_ah,
                     float* __restrict__ out) {
    int r    = blockIdx.x * 8 + (threadIdx.x >> 5);
    int lane = threadIdx.x & 31;
    const float4* wa4 = (const float4*)(W_ah + (size_t)r * (E + H));
    const float4* c4  = (const float4*)g_context;
    const float4* h4  = (const float4*)g_h;
    float s = 0.f;
#pragma unroll
    for (int q = 0; q < 8; q++) {
        int k = lane + 32 * q;
        float4 a = wa4[k];        float4 b = c4[k];
        s += a.x * b.x + a.y * b.y + a.z * b.z + a.w * b.w;
        float4 a2 = wa4[256 + k]; float4 b2 = h4[k];
        s += a2.x * b2.x + a2.y * b2.y + a2.z * b2.z + a2.w * b2.w;
    }
    s = warp_sum(s);
    if (lane == 0) {
        float xt = tanhf(s + b_ah[r]);
        g_xt[r] = xt;
        out[V + 2 * H + r] = xt;
    }
}

// ---------------- K7: logits = W_out @ x_t + b_out, + per-block exp-sum partials ----
__global__ void k_logits(const float* __restrict__ W_out, const float* __restrict__ b_out,
                         float* __restrict__ out) {
    __shared__ float sred[8];
    int tid  = threadIdx.x;
    int wid  = tid >> 5;
    int lane = tid & 31;
    int r    = blockIdx.x * 8 + wid;
    const float4* w4 = (const float4*)(W_out + (size_t)r * H);
    const float4* x4 = (const float4*)g_xt;
    float s = 0.f;
#pragma unroll
    for (int q = 0; q < 8; q++) {
        int k = lane + 32 * q;
        float4 a = w4[k]; float4 b = x4[k];
        s += a.x * b.x + a.y * b.y + a.z * b.z + a.w * b.w;
    }
    s = warp_sum(s);
    if (lane == 0) {
        float val = s + b_out[r];
        out[r] = val;
        sred[wid] = expf(val);
    }
    __syncthreads();
    if (tid == 0) {
        float p = 0.f;
#pragma unroll
        for (int i = 0; i < 8; i++) p += sred[i];
        g_lp[blockIdx.x] = p;
    }
}

// ---------------- K8: log-softmax: out[i] -= log(sum exp) (redundant partial reduce) ----
__global__ void k_logsoftmax(float* __restrict__ out) {
    __shared__ float red[256];
    int tid = threadIdx.x;
    float p = 0.f;
    for (int i = tid; i < NLOGB; i += 256) p += g_lp[i];
    red[tid] = p; __syncthreads();
    for (int o = 128; o; o >>= 1) { if (tid < o) red[tid] += red[tid + o]; __syncthreads(); }
    float l = logf(red[0]);
    int i = blockIdx.x * 256 + tid;
    out[i] = out[i] - l;
}

// ---------------- launch ----------------
extern "C" void kernel_launch(void* const* d_in, const int* in_sizes, int n_in,
                              void* d_out, int out_size) {
    const float* enc      = (const float*)d_in[0];
    const int*   word     = (const int*)  d_in[1];
    const float* last_ctx = (const float*)d_in[2];
    const float* h0       = (const float*)d_in[3];
    const float* c0       = (const float*)d_in[4];
    const float* emb      = (const float*)d_in[5];
    const float* W_ih     = (const float*)d_in[6];
    const float* b_ih     = (const float*)d_in[7];
    const float* W_hh     = (const float*)d_in[8];
    const float* b_hh     = (const float*)d_in[9];
    const float* W_att    = (const float*)d_in[10];
    const float* b_att    = (const float*)d_in[11];
    const float* v        = (const float*)d_in[12];
    const float* W_ah     = (const float*)d_in[13];
    const float* b_ah     = (const float*)d_in[14];
    const float* W_out    = (const float*)d_in[15];
    const float* b_out    = (const float*)d_in[16];
    float* out = (float*)d_out;

    cudaFuncSetAttribute(k_att_gemm, cudaFuncAttributeMaxDynamicSharedMemorySize, ATT_SMEM_BYTES);

    // fork: LSTM chain on side stream, attention GEMM on main stream
    cudaStream_t sB;
    cudaStreamCreateWithFlags(&sB, cudaStreamNonBlocking);
    cudaEvent_t e0, eB;
    cudaEventCreateWithFlags(&e0, cudaEventDisableTiming);
    cudaEventCreateWithFlags(&eB, cudaEventDisableTiming);

    cudaEventRecord(e0, 0);
    cudaStreamWaitEvent(sB, e0, 0);
    k_gates<<<512, 256, 0, sB>>>(W_ih, b_ih, W_hh, b_hh, last_ctx, emb, word, h0);
    k_cell_u<<<128, 256, 0, sB>>>(c0, W_att, b_att, out);
    cudaEventRecord(eB, sB);

    dim3 g3(S / BM, H / BN);
    k_att_gemm<<<g3, 256, ATT_SMEM_BYTES>>>(enc, W_att);

    cudaStreamWaitEvent(0, eB, 0);
    k_score<<<S, 256>>>(v);
    dim3 g5(E / 256, S / 64);
    k_ctx<<<g5, 256>>>(enc, out);
    k_xt<<<128, 256>>>(W_ah, b_ah, out);
    k_logits<<<NLOGB, 256>>>(W_out, b_out, out);
    k_logsoftmax<<<V / 256, 256>>>(out);
}